// round 1
// baseline (speedup 1.0000x reference)
#include <cuda_runtime.h>

// Problem constants
#define M_DIM   16
#define DICT    64
#define N_DIM   8
#define B_DIM   8192
#define KTERMS  24
#define BDIM    256

// 1/k table for the Taylor recurrence (k=0 unused)
__device__ __constant__ float INVK[KTERMS + 1] = {
    0.0f,
    1.0f / 1,  1.0f / 2,  1.0f / 3,  1.0f / 4,  1.0f / 5,  1.0f / 6,
    1.0f / 7,  1.0f / 8,  1.0f / 9,  1.0f / 10, 1.0f / 11, 1.0f / 12,
    1.0f / 13, 1.0f / 14, 1.0f / 15, 1.0f / 16, 1.0f / 17, 1.0f / 18,
    1.0f / 19, 1.0f / 20, 1.0f / 21, 1.0f / 22, 1.0f / 23, 1.0f / 24
};

// Grid: (B/256, DICT). Block handles 256 consecutive b for one dictionary slot s.
// Each thread: builds its 8x8 A in registers, runs 24-term Taylor expm(A)*x.
__global__ __launch_bounds__(BDIM, 2)
void transop_expm_kernel(const float* __restrict__ x,
                         const float* __restrict__ c,
                         const float* __restrict__ psi,
                         float* __restrict__ out)
{
    const int s = blockIdx.y;                       // dictionary slot
    const int b = blockIdx.x * BDIM + threadIdx.x;  // batch element

    // psi[m, s, :, :] slice: 16 m-rows x 64 entries = 1024 floats = 256 float4.
    __shared__ float4 psi_s[M_DIM * 16];

    {
        // Cooperative load: 256 threads, 256 float4s, one each.
        // Element (m, nk) lives at psi[(m*DICT + s)*64 + nk]; as float4:
        // index (m*DICT + s)*16 + q.
        const int t = threadIdx.x;
        const int m = t >> 4;        // 0..15
        const int q = t & 15;        // 0..15 (float4 within the 64-entry tile)
        psi_s[t] = reinterpret_cast<const float4*>(psi)[(m * DICT + s) * 16 + q];
    }
    __syncthreads();

    // Load c[b, :] (16 floats, contiguous => dense across the warp).
    float cm[M_DIM];
    {
        const float4* c4 = reinterpret_cast<const float4*>(c + (size_t)b * M_DIM);
        float4 c0 = c4[0], c1 = c4[1], c2 = c4[2], c3 = c4[3];
        cm[0] = c0.x; cm[1] = c0.y; cm[2]  = c0.z; cm[3]  = c0.w;
        cm[4] = c1.x; cm[5] = c1.y; cm[6]  = c1.z; cm[7]  = c1.w;
        cm[8] = c2.x; cm[9] = c2.y; cm[10] = c2.z; cm[11] = c2.w;
        cm[12]= c3.x; cm[13]= c3.y; cm[14] = c3.z; cm[15] = c3.w;
    }

    // Build A[n*8+k] = sum_m cm[m] * psi_s[m][nk]  (broadcast LDS.128, no conflicts)
    float A[64];
    #pragma unroll
    for (int i = 0; i < 64; i++) A[i] = 0.0f;

    #pragma unroll
    for (int m = 0; m < M_DIM; m++) {
        const float cv = cm[m];
        #pragma unroll
        for (int q = 0; q < 16; q++) {
            float4 p = psi_s[m * 16 + q];
            A[4 * q + 0] = fmaf(cv, p.x, A[4 * q + 0]);
            A[4 * q + 1] = fmaf(cv, p.y, A[4 * q + 1]);
            A[4 * q + 2] = fmaf(cv, p.z, A[4 * q + 2]);
            A[4 * q + 3] = fmaf(cv, p.w, A[4 * q + 3]);
        }
    }

    // Load x block: x[b, s*8 .. s*8+8) — contiguous 32B per thread.
    float v[N_DIM], acc[N_DIM];
    {
        const float4* xp = reinterpret_cast<const float4*>(
            x + (size_t)b * (DICT * N_DIM) + s * N_DIM);
        float4 x0 = xp[0], x1 = xp[1];
        v[0] = x0.x; v[1] = x0.y; v[2] = x0.z; v[3] = x0.w;
        v[4] = x1.x; v[5] = x1.y; v[6] = x1.z; v[7] = x1.w;
        #pragma unroll
        for (int i = 0; i < N_DIM; i++) acc[i] = v[i];
    }

    // Taylor: acc = sum_{k=0..K} A^k x / k!   via  v <- (A v)/k ; acc += v
    #pragma unroll 1
    for (int k = 1; k <= KTERMS; k++) {
        float t[N_DIM];
        #pragma unroll
        for (int n = 0; n < N_DIM; n++) {
            float sum = A[n * 8 + 0] * v[0];
            #pragma unroll
            for (int j = 1; j < N_DIM; j++)
                sum = fmaf(A[n * 8 + j], v[j], sum);
            t[n] = sum;
        }
        const float ik = INVK[k];
        #pragma unroll
        for (int i = 0; i < N_DIM; i++) {
            v[i] = t[i] * ik;
            acc[i] = fmaf(t[i], ik, acc[i]);
        }
    }

    // Store out[b, s*8 .. s*8+8)
    {
        float4* op = reinterpret_cast<float4*>(
            out + (size_t)b * (DICT * N_DIM) + s * N_DIM);
        op[0] = make_float4(acc[0], acc[1], acc[2], acc[3]);
        op[1] = make_float4(acc[4], acc[5], acc[6], acc[7]);
    }
}

extern "C" void kernel_launch(void* const* d_in, const int* in_sizes, int n_in,
                              void* d_out, int out_size)
{
    const float* x   = (const float*)d_in[0];  // (8192, 512)
    const float* c   = (const float*)d_in[1];  // (8192, 16)
    const float* psi = (const float*)d_in[2];  // (16, 64, 8, 8)
    float* out = (float*)d_out;                // (8192, 512)

    dim3 grid(B_DIM / BDIM, DICT);
    transop_expm_kernel<<<grid, BDIM>>>(x, c, psi, out);
}